// round 6
// baseline (speedup 1.0000x reference)
#include <cuda_runtime.h>
#include <cuda_fp16.h>
#include <mma.h>

using namespace nvcuda;

#define S 128
#define H 64
#define LDH 72     // leading dim for half h1 rows (144 B = 9*16)
#define LDF 68     // leading dim for float h2 rows (272 B = 17*16, conflict-free float4)

// Dynamic shared memory layout (bytes):
//   [0, 36864)      aliased: { h1_hi half[128*LDH] @0 ; h1_lo half[128*LDH] @18432 }
//                   later:   h2 float[128*LDF] (34816 B, fits)
//   [36864, 37632)  sW1   float[3*64]
//   [37632, 37888)  sb1   float[64]
//   [37888, 38144)  sb2   float[64]
//   [38144, 38400)  sWsig float[64]
//   [38400, 39168)  sWrgb float[3*64] (transposed [c][j])
//   [39168, 39184)  sWprod float[4]
//   [39184, 39232)  sSum  float[4][3]
#define SMEM_BYTES 39232

// Pre-split W2 (Markidis hi/lo fp16), packed once per launch by pack_w2_kernel.
__device__ __align__(16) __half gW2hi[H * H];
__device__ __align__(16) __half gW2lo[H * H];

__global__ void pack_w2_kernel(const float* __restrict__ W2)
{
    const int i = blockIdx.x * blockDim.x + threadIdx.x;
    if (i < H * H) {
        const float w = W2[i];
        const __half hi = __float2half_rn(w);
        gW2hi[i] = hi;
        gW2lo[i] = __float2half_rn(w - __half2float(hi));
    }
}

__global__ __launch_bounds__(128, 4)
void render_kernel(const float* __restrict__ rays_o,
                   const float* __restrict__ rays_d,
                   const float* __restrict__ nearv,
                   const float* __restrict__ farv,
                   const float* __restrict__ jitter,
                   const float* __restrict__ density,
                   const float* __restrict__ W1,
                   const float* __restrict__ b1,
                   const float* __restrict__ b2,
                   const float* __restrict__ Wsig,
                   const float* __restrict__ bsig,
                   const float* __restrict__ Wrgb,
                   const float* __restrict__ brgb,
                   float* __restrict__ out)
{
    extern __shared__ __align__(16) char smem[];
    __half* hH1hi = reinterpret_cast<__half*>(smem);
    __half* hH1lo = reinterpret_cast<__half*>(smem + 18432);
    float*  fH2   = reinterpret_cast<float*>(smem);            // aliases h1 pair
    float*  sW1   = reinterpret_cast<float*>(smem + 36864);
    float*  sb1   = reinterpret_cast<float*>(smem + 37632);
    float*  sb2   = reinterpret_cast<float*>(smem + 37888);
    float*  sWsig = reinterpret_cast<float*>(smem + 38144);
    float*  sWrgb = reinterpret_cast<float*>(smem + 38400);
    float*  sWprod = reinterpret_cast<float*>(smem + 39168);
    float*  sSum   = reinterpret_cast<float*>(smem + 39184);   // [4][3]

    const int t    = threadIdx.x;
    const int lane = t & 31;
    const int warp = t >> 5;
    const int ray  = blockIdx.x;

    // ---- stage small weights (visible after the syncthreads_or below) ----
    for (int i = t; i < 3 * H; i += 128) sW1[i] = W1[i];
    for (int i = t; i < 3 * H; i += 128) {
        const int j = i % H, c = i / H;
        sWrgb[c * H + j] = Wrgb[j * 3 + c];
    }
    if (t < H) { sb1[t] = b1[t]; sb2[t] = b2[t]; sWsig[t] = Wsig[t]; }

    // ---- per-sample ray setup + occupancy-grid mask ----
    const float ox = rays_o[ray * 3 + 0];
    const float oy = rays_o[ray * 3 + 1];
    const float oz = rays_o[ray * 3 + 2];
    const float dx = rays_d[ray * 3 + 0];
    const float dy = rays_d[ray * 3 + 1];
    const float dz = rays_d[ray * 3 + 2];
    const float nr = nearv[ray];
    const float fr = farv[ray];
    const float step = (fr - nr) * (1.0f / (float)S);
    const float z = nr + (float)t * step;

    const float p0x = ox + z * dx;
    const float p0y = oy + z * dy;
    const float p0z = oz + z * dz;
    const float ux = (p0x - (-1.25f)) / 2.5f;
    const float uy = (p0y - (-1.55f)) / 2.5f;
    const float uz = (p0z - (-1.25f)) / 2.5f;
    const int ix = (int)floorf(ux * 64.0f);
    const int iy = (int)floorf(uy * 64.0f);
    const int iz = (int)floorf(uz * 64.0f);
    const bool inb = (ix >= 0) & (ix < 64) & (iy >= 0) & (iy < 64) & (iz >= 0) & (iz < 64);
    const int cx = min(max(ix, 0), 63);
    const int cy = min(max(iy, 0), 63);
    const int cz = min(max(iz, 0), 63);
    const bool occ = density[(cx * 64 + cy) * 64 + cz] > 0.5f;
    const bool mask = occ && inb;

    // Full barrier (with reduction): also makes small-weight staging visible.
    const int any_active = __syncthreads_or(mask ? 1 : 0);
    if (!any_active) {
        if (t == 0) {
            out[ray * 3 + 0] = 1.0f;
            out[ray * 3 + 1] = 1.0f;
            out[ray * 3 + 2] = 1.0f;
        }
        return;
    }

    // Warp-level skip: if all 32 samples of this warp are culled, the MLP
    // rows of this warp are never read (heads run only under `mask`).
    const unsigned wball = __ballot_sync(0xffffffffu, mask);
    const bool warp_active = (wball != 0u);

    const float zv = mask ? z : 0.0f;
    const float zj = zv + jitter[ray * S + t] * step;
    const float px = ox + zj * dx;
    const float py = oy + zj * dy;
    const float pz = oz + zj * dz;

    // ---- layer 1 (scalar fp32, K=3): h1 split into hi + lo fp16 rows ----
    if (warp_active) {
        __half* hrowHi = hH1hi + t * LDH;
        __half* hrowLo = hH1lo + t * LDH;
        #pragma unroll
        for (int j = 0; j < H; j++) {
            float v = sb1[j];
            v = fmaf(px, sW1[j], v);
            v = fmaf(py, sW1[H + j], v);
            v = fmaf(pz, sW1[2 * H + j], v);
            v = fmaxf(v, 0.0f);
            const __half vhi = __float2half_rn(v);
            const __half vlo = __float2half_rn(v - __half2float(vhi));
            hrowHi[j] = vhi;
            hrowLo[j] = vlo;
        }
    }
    __syncthreads();

    // ---- layer 2: h2 = h_hi*w_hi + h_hi*w_lo + h_lo*w_hi (fp32 accum) ----
    // B fragments load straight from global (L1-hot across the whole launch).
    wmma::fragment<wmma::accumulator, 16, 16, 16, float> c[2][4];
    if (warp_active) {
        #pragma unroll
        for (int mt = 0; mt < 2; mt++)
            #pragma unroll
            for (int nt = 0; nt < 4; nt++)
                wmma::fill_fragment(c[mt][nt], 0.0f);

        #pragma unroll
        for (int k = 0; k < 4; k++) {
            wmma::fragment<wmma::matrix_a, 16, 16, 16, __half, wmma::row_major> aHi0, aHi1, aLo0, aLo1;
            wmma::load_matrix_sync(aHi0, hH1hi + (warp * 32) * LDH + k * 16, LDH);
            wmma::load_matrix_sync(aHi1, hH1hi + (warp * 32 + 16) * LDH + k * 16, LDH);
            wmma::load_matrix_sync(aLo0, hH1lo + (warp * 32) * LDH + k * 16, LDH);
            wmma::load_matrix_sync(aLo1, hH1lo + (warp * 32 + 16) * LDH + k * 16, LDH);
            #pragma unroll
            for (int nt = 0; nt < 4; nt++) {
                wmma::fragment<wmma::matrix_b, 16, 16, 16, __half, wmma::row_major> bHi, bLo;
                wmma::load_matrix_sync(bHi, gW2hi + (k * 16) * H + nt * 16, H);
                wmma::load_matrix_sync(bLo, gW2lo + (k * 16) * H + nt * 16, H);
                wmma::mma_sync(c[0][nt], aHi0, bHi, c[0][nt]);
                wmma::mma_sync(c[1][nt], aHi1, bHi, c[1][nt]);
                wmma::mma_sync(c[0][nt], aHi0, bLo, c[0][nt]);
                wmma::mma_sync(c[1][nt], aHi1, bLo, c[1][nt]);
                wmma::mma_sync(c[0][nt], aLo0, bHi, c[0][nt]);
                wmma::mma_sync(c[1][nt], aLo1, bHi, c[1][nt]);
            }
        }
    }

    // fH2 aliases the h1 buffers: all MMA reads must finish before stores.
    __syncthreads();
    if (warp_active) {
        #pragma unroll
        for (int mt = 0; mt < 2; mt++)
            #pragma unroll
            for (int nt = 0; nt < 4; nt++)
                wmma::store_matrix_sync(fH2 + (warp * 32 + mt * 16) * LDF + nt * 16,
                                        c[mt][nt], LDF, wmma::mem_row_major);
    }
    __syncthreads();

    // ---- heads (scalar fp32), only for active samples ----
    float alpha = 0.0f, r = 0.0f, g = 0.0f, b = 0.0f;
    if (mask) {
        float sigma = bsig[0];
        float cr = brgb[0], cg = brgb[1], cb = brgb[2];
        const float4* hrow = reinterpret_cast<const float4*>(fH2 + t * LDF);
        #pragma unroll
        for (int jq = 0; jq < 16; jq++) {
            const float4 hv = hrow[jq];
            const int j = jq * 4;
            const float h0 = fmaxf(hv.x + sb2[j + 0], 0.0f);
            const float h1 = fmaxf(hv.y + sb2[j + 1], 0.0f);
            const float h2 = fmaxf(hv.z + sb2[j + 2], 0.0f);
            const float h3 = fmaxf(hv.w + sb2[j + 3], 0.0f);
            sigma = fmaf(h0, sWsig[j + 0], sigma);
            sigma = fmaf(h1, sWsig[j + 1], sigma);
            sigma = fmaf(h2, sWsig[j + 2], sigma);
            sigma = fmaf(h3, sWsig[j + 3], sigma);
            cr = fmaf(h0, sWrgb[j + 0], cr);
            cr = fmaf(h1, sWrgb[j + 1], cr);
            cr = fmaf(h2, sWrgb[j + 2], cr);
            cr = fmaf(h3, sWrgb[j + 3], cr);
            cg = fmaf(h0, sWrgb[H + j + 0], cg);
            cg = fmaf(h1, sWrgb[H + j + 1], cg);
            cg = fmaf(h2, sWrgb[H + j + 2], cg);
            cg = fmaf(h3, sWrgb[H + j + 3], cg);
            cb = fmaf(h0, sWrgb[2 * H + j + 0], cb);
            cb = fmaf(h1, sWrgb[2 * H + j + 1], cb);
            cb = fmaf(h2, sWrgb[2 * H + j + 2], cb);
            cb = fmaf(h3, sWrgb[2 * H + j + 3], cb);
        }
        const float tau = fmaxf(sigma, 0.0f) * step;
        alpha = 1.0f - __expf(-tau);
        r = 1.0f / (1.0f + __expf(-cr));
        g = 1.0f / (1.0f + __expf(-cg));
        b = 1.0f / (1.0f + __expf(-cb));
    }

    // ---- composite: warp-shuffle scan + cross-warp combine ----
    const float f = 1.0f - alpha + 1e-10f;
    float incl = f;
    #pragma unroll
    for (int off = 1; off < 32; off <<= 1) {
        const float v = __shfl_up_sync(0xffffffffu, incl, off);
        if (lane >= off) incl *= v;
    }
    const float wtot = __shfl_sync(0xffffffffu, incl, 31);
    if (lane == 0) sWprod[warp] = wtot;
    __syncthreads();

    float pre = 1.0f;
    #pragma unroll
    for (int i = 0; i < 4; i++) if (i < warp) pre *= sWprod[i];

    float excl = __shfl_up_sync(0xffffffffu, incl, 1);
    if (lane == 0) excl = 1.0f;

    const float w = alpha * pre * excl;
    float wr = w * r, wg = w * g, wb = w * b;
    #pragma unroll
    for (int off = 16; off > 0; off >>= 1) {
        wr += __shfl_down_sync(0xffffffffu, wr, off);
        wg += __shfl_down_sync(0xffffffffu, wg, off);
        wb += __shfl_down_sync(0xffffffffu, wb, off);
    }
    if (lane == 0) { sSum[warp * 3 + 0] = wr; sSum[warp * 3 + 1] = wg; sSum[warp * 3 + 2] = wb; }
    __syncthreads();

    if (t == 0) {
        const float no_hit = sWprod[0] * sWprod[1] * sWprod[2] * sWprod[3];
        float c0 = no_hit, c1 = no_hit, c2 = no_hit;
        #pragma unroll
        for (int i = 0; i < 4; i++) {
            c0 += sSum[i * 3 + 0];
            c1 += sSum[i * 3 + 1];
            c2 += sSum[i * 3 + 2];
        }
        out[ray * 3 + 0] = c0;
        out[ray * 3 + 1] = c1;
        out[ray * 3 + 2] = c2;
    }
}

extern "C" void kernel_launch(void* const* d_in, const int* in_sizes, int n_in,
                              void* d_out, int out_size)
{
    const float* rays_o  = (const float*)d_in[0];
    const float* rays_d  = (const float*)d_in[1];
    const float* nearv   = (const float*)d_in[2];
    const float* farv    = (const float*)d_in[3];
    const float* jitter  = (const float*)d_in[4];
    const float* density = (const float*)d_in[5];
    const float* W1      = (const float*)d_in[6];
    const float* b1      = (const float*)d_in[7];
    const float* W2      = (const float*)d_in[8];
    const float* b2      = (const float*)d_in[9];
    const float* Wsig    = (const float*)d_in[10];
    const float* bsig    = (const float*)d_in[11];
    const float* Wrgb    = (const float*)d_in[12];
    const float* brgb    = (const float*)d_in[13];

    const int n_rays = in_sizes[2];   // near has one entry per ray

    cudaFuncSetAttribute(render_kernel, cudaFuncAttributeMaxDynamicSharedMemorySize, SMEM_BYTES);

    pack_w2_kernel<<<(H * H + 127) / 128, 128>>>(W2);
    render_kernel<<<n_rays, 128, SMEM_BYTES>>>(rays_o, rays_d, nearv, farv, jitter, density,
                                               W1, b1, b2, Wsig, bsig, Wrgb, brgb,
                                               (float*)d_out);
}

// round 7
// speedup vs baseline: 1.2982x; 1.2982x over previous
#include <cuda_runtime.h>
#include <cuda_fp16.h>
#include <mma.h>

using namespace nvcuda;

#define S 128
#define H 64
#define LDH 72     // leading dim for half tiles (144 B = 9*16, LDSM conflict-free)
#define LDF 68     // leading dim for float h2 rows (272 B = 17*16, conflict-free float4)

// Dynamic shared memory layout (bytes):
//   [0, 36864)      aliased: { h1_hi half[128*LDH] @0 ; h1_lo half[128*LDH] @18432 }
//                   later:   h2 float[128*LDF] = 34816 B (fits)
//   [36864, 46080)  W2_hi half[64*LDH]  (copied pre-packed from global)
//   [46080, 55296)  W2_lo half[64*LDH]
//   [55296, 55312)  sWprod float[4]
//   [55312, 55360)  sSum  float[4][3]
#define SMEM_BYTES 55360

// Pre-split W2 (Markidis hi/lo fp16) in the FINAL padded smem layout,
// packed once per launch. __device__ globals are zero-initialized, so the
// LDH padding columns stay zero (never read by fragments anyway).
__device__ __align__(16) __half gW2hi[H * LDH];
__device__ __align__(16) __half gW2lo[H * LDH];

__global__ void pack_w2_kernel(const float* __restrict__ W2)
{
    const int i = blockIdx.x * blockDim.x + threadIdx.x;
    if (i < H * H) {
        const int k = i >> 6, j = i & 63;
        const float w = W2[i];
        const __half hi = __float2half_rn(w);
        gW2hi[k * LDH + j] = hi;
        gW2lo[k * LDH + j] = __float2half_rn(w - __half2float(hi));
    }
}

__global__ __launch_bounds__(128, 4)
void render_kernel(const float* __restrict__ rays_o,
                   const float* __restrict__ rays_d,
                   const float* __restrict__ nearv,
                   const float* __restrict__ farv,
                   const float* __restrict__ jitter,
                   const float* __restrict__ density,
                   const float* __restrict__ W1,
                   const float* __restrict__ b1,
                   const float* __restrict__ b2,
                   const float* __restrict__ Wsig,
                   const float* __restrict__ bsig,
                   const float* __restrict__ Wrgb,
                   const float* __restrict__ brgb,
                   float* __restrict__ out)
{
    extern __shared__ __align__(16) char smem[];
    __half* hH1hi = reinterpret_cast<__half*>(smem);
    __half* hH1lo = reinterpret_cast<__half*>(smem + 18432);
    float*  fH2   = reinterpret_cast<float*>(smem);            // aliases h1 pair
    __half* sW2hi = reinterpret_cast<__half*>(smem + 36864);
    __half* sW2lo = reinterpret_cast<__half*>(smem + 46080);
    float*  sWprod = reinterpret_cast<float*>(smem + 55296);
    float*  sSum   = reinterpret_cast<float*>(smem + 55312);   // [4][3]

    const int t    = threadIdx.x;
    const int lane = t & 31;
    const int warp = t >> 5;
    const int ray  = blockIdx.x;

    // ---- per-sample ray setup + occupancy-grid mask ----
    const float ox = rays_o[ray * 3 + 0];
    const float oy = rays_o[ray * 3 + 1];
    const float oz = rays_o[ray * 3 + 2];
    const float dx = rays_d[ray * 3 + 0];
    const float dy = rays_d[ray * 3 + 1];
    const float dz = rays_d[ray * 3 + 2];
    const float nr = nearv[ray];
    const float fr = farv[ray];
    const float step = (fr - nr) * (1.0f / (float)S);
    const float z = nr + (float)t * step;

    const float p0x = ox + z * dx;
    const float p0y = oy + z * dy;
    const float p0z = oz + z * dz;
    const float ux = (p0x - (-1.25f)) / 2.5f;
    const float uy = (p0y - (-1.55f)) / 2.5f;
    const float uz = (p0z - (-1.25f)) / 2.5f;
    const int ix = (int)floorf(ux * 64.0f);
    const int iy = (int)floorf(uy * 64.0f);
    const int iz = (int)floorf(uz * 64.0f);
    const bool inb = (ix >= 0) & (ix < 64) & (iy >= 0) & (iy < 64) & (iz >= 0) & (iz < 64);
    const int cx = min(max(ix, 0), 63);
    const int cy = min(max(iy, 0), 63);
    const int cz = min(max(iz, 0), 63);
    const bool occ = density[(cx * 64 + cy) * 64 + cz] > 0.5f;
    const bool mask = occ && inb;

    // Whole-ray empty? -> exact white (1 - 0 + 1e-10 rounds to 1.0f).
    const int any_active = __syncthreads_or(mask ? 1 : 0);
    if (!any_active) {
        if (t == 0) {
            out[ray * 3 + 0] = 1.0f;
            out[ray * 3 + 1] = 1.0f;
            out[ray * 3 + 2] = 1.0f;
        }
        return;
    }

    // ---- copy pre-packed W2 hi/lo into shared (pure int4 memcpy, no converts) ----
    {
        const int4* src_hi = reinterpret_cast<const int4*>(gW2hi);
        const int4* src_lo = reinterpret_cast<const int4*>(gW2lo);
        int4* dst_hi = reinterpret_cast<int4*>(sW2hi);
        int4* dst_lo = reinterpret_cast<int4*>(sW2lo);
        #pragma unroll
        for (int i = t; i < (H * LDH * 2) / 16; i += 128) {   // 1152 int4 each
            dst_hi[i] = src_hi[i];
            dst_lo[i] = src_lo[i];
        }
    }

    // Warp-level skip: if all 32 samples of this warp are culled, the MLP
    // rows of this warp are never read (heads run only under `mask`).
    const unsigned wball = __ballot_sync(0xffffffffu, mask);
    const bool warp_active = (wball != 0u);

    const float zv = mask ? z : 0.0f;
    const float zj = zv + jitter[ray * S + t] * step;
    const float px = ox + zj * dx;
    const float py = oy + zj * dy;
    const float pz = oz + zj * dz;

    // ---- layer 1 (scalar fp32, K=3): weights via uniform L1-hot LDG ----
    if (warp_active) {
        __half* hrowHi = hH1hi + t * LDH;
        __half* hrowLo = hH1lo + t * LDH;
        #pragma unroll
        for (int j = 0; j < H; j++) {
            float v = b1[j];
            v = fmaf(px, W1[j], v);
            v = fmaf(py, W1[H + j], v);
            v = fmaf(pz, W1[2 * H + j], v);
            v = fmaxf(v, 0.0f);
            const __half vhi = __float2half_rn(v);
            const __half vlo = __float2half_rn(v - __half2float(vhi));
            hrowHi[j] = vhi;
            hrowLo[j] = vlo;
        }
    }
    __syncthreads();   // h1 rows + W2 smem copy visible to all warps

    // ---- layer 2: h2 = h_hi*w_hi + h_hi*w_lo + h_lo*w_hi (fp32 accum) ----
    wmma::fragment<wmma::accumulator, 16, 16, 16, float> c[2][4];
    if (warp_active) {
        #pragma unroll
        for (int mt = 0; mt < 2; mt++)
            #pragma unroll
            for (int nt = 0; nt < 4; nt++)
                wmma::fill_fragment(c[mt][nt], 0.0f);

        #pragma unroll
        for (int k = 0; k < 4; k++) {
            wmma::fragment<wmma::matrix_a, 16, 16, 16, __half, wmma::row_major> aHi0, aHi1, aLo0, aLo1;
            wmma::load_matrix_sync(aHi0, hH1hi + (warp * 32) * LDH + k * 16, LDH);
            wmma::load_matrix_sync(aHi1, hH1hi + (warp * 32 + 16) * LDH + k * 16, LDH);
            wmma::load_matrix_sync(aLo0, hH1lo + (warp * 32) * LDH + k * 16, LDH);
            wmma::load_matrix_sync(aLo1, hH1lo + (warp * 32 + 16) * LDH + k * 16, LDH);
            #pragma unroll
            for (int nt = 0; nt < 4; nt++) {
                wmma::fragment<wmma::matrix_b, 16, 16, 16, __half, wmma::row_major> bHi, bLo;
                wmma::load_matrix_sync(bHi, sW2hi + (k * 16) * LDH + nt * 16, LDH);
                wmma::load_matrix_sync(bLo, sW2lo + (k * 16) * LDH + nt * 16, LDH);
                wmma::mma_sync(c[0][nt], aHi0, bHi, c[0][nt]);
                wmma::mma_sync(c[1][nt], aHi1, bHi, c[1][nt]);
                wmma::mma_sync(c[0][nt], aHi0, bLo, c[0][nt]);
                wmma::mma_sync(c[1][nt], aHi1, bLo, c[1][nt]);
                wmma::mma_sync(c[0][nt], aLo0, bHi, c[0][nt]);
                wmma::mma_sync(c[1][nt], aLo1, bHi, c[1][nt]);
            }
        }
    }

    // fH2 aliases the h1 buffers: all MMA reads must finish before stores.
    __syncthreads();
    if (warp_active) {
        #pragma unroll
        for (int mt = 0; mt < 2; mt++)
            #pragma unroll
            for (int nt = 0; nt < 4; nt++)
                wmma::store_matrix_sync(fH2 + (warp * 32 + mt * 16) * LDF + nt * 16,
                                        c[mt][nt], LDF, wmma::mem_row_major);
    }
    __syncthreads();

    // ---- heads (scalar fp32), only for active samples; weights via uniform LDG ----
    float alpha = 0.0f, r = 0.0f, g = 0.0f, b = 0.0f;
    if (mask) {
        float sigma = bsig[0];
        float cr = brgb[0], cg = brgb[1], cb = brgb[2];
        const float4* hrow = reinterpret_cast<const float4*>(fH2 + t * LDF);
        #pragma unroll
        for (int jq = 0; jq < 16; jq++) {
            const float4 hv = hrow[jq];
            const int j = jq * 4;
            const float h0 = fmaxf(hv.x + b2[j + 0], 0.0f);
            const float h1 = fmaxf(hv.y + b2[j + 1], 0.0f);
            const float h2 = fmaxf(hv.z + b2[j + 2], 0.0f);
            const float h3 = fmaxf(hv.w + b2[j + 3], 0.0f);
            sigma = fmaf(h0, Wsig[j + 0], sigma);
            sigma = fmaf(h1, Wsig[j + 1], sigma);
            sigma = fmaf(h2, Wsig[j + 2], sigma);
            sigma = fmaf(h3, Wsig[j + 3], sigma);
            cr = fmaf(h0, Wrgb[(j + 0) * 3 + 0], cr);
            cg = fmaf(h0, Wrgb[(j + 0) * 3 + 1], cg);
            cb = fmaf(h0, Wrgb[(j + 0) * 3 + 2], cb);
            cr = fmaf(h1, Wrgb[(j + 1) * 3 + 0], cr);
            cg = fmaf(h1, Wrgb[(j + 1) * 3 + 1], cg);
            cb = fmaf(h1, Wrgb[(j + 1) * 3 + 2], cb);
            cr = fmaf(h2, Wrgb[(j + 2) * 3 + 0], cr);
            cg = fmaf(h2, Wrgb[(j + 2) * 3 + 1], cg);
            cb = fmaf(h2, Wrgb[(j + 2) * 3 + 2], cb);
            cr = fmaf(h3, Wrgb[(j + 3) * 3 + 0], cr);
            cg = fmaf(h3, Wrgb[(j + 3) * 3 + 1], cg);
            cb = fmaf(h3, Wrgb[(j + 3) * 3 + 2], cb);
        }
        const float tau = fmaxf(sigma, 0.0f) * step;
        alpha = 1.0f - __expf(-tau);
        r = 1.0f / (1.0f + __expf(-cr));
        g = 1.0f / (1.0f + __expf(-cg));
        b = 1.0f / (1.0f + __expf(-cb));
    }

    // ---- composite: warp-shuffle scan + cross-warp combine ----
    const float f = 1.0f - alpha + 1e-10f;
    float incl = f;
    #pragma unroll
    for (int off = 1; off < 32; off <<= 1) {
        const float v = __shfl_up_sync(0xffffffffu, incl, off);
        if (lane >= off) incl *= v;
    }
    const float wtot = __shfl_sync(0xffffffffu, incl, 31);
    if (lane == 0) sWprod[warp] = wtot;
    __syncthreads();

    float pre = 1.0f;
    #pragma unroll
    for (int i = 0; i < 4; i++) if (i < warp) pre *= sWprod[i];

    float excl = __shfl_up_sync(0xffffffffu, incl, 1);
    if (lane == 0) excl = 1.0f;

    const float w = alpha * pre * excl;
    float wr = w * r, wg = w * g, wb = w * b;
    #pragma unroll
    for (int off = 16; off > 0; off >>= 1) {
        wr += __shfl_down_sync(0xffffffffu, wr, off);
        wg += __shfl_down_sync(0xffffffffu, wg, off);
        wb += __shfl_down_sync(0xffffffffu, wb, off);
    }
    if (lane == 0) { sSum[warp * 3 + 0] = wr; sSum[warp * 3 + 1] = wg; sSum[warp * 3 + 2] = wb; }
    __syncthreads();

    if (t == 0) {
        const float no_hit = sWprod[0] * sWprod[1] * sWprod[2] * sWprod[3];
        float c0 = no_hit, c1 = no_hit, c2 = no_hit;
        #pragma unroll
        for (int i = 0; i < 4; i++) {
            c0 += sSum[i * 3 + 0];
            c1 += sSum[i * 3 + 1];
            c2 += sSum[i * 3 + 2];
        }
        out[ray * 3 + 0] = c0;
        out[ray * 3 + 1] = c1;
        out[ray * 3 + 2] = c2;
    }
}

extern "C" void kernel_launch(void* const* d_in, const int* in_sizes, int n_in,
                              void* d_out, int out_size)
{
    const float* rays_o  = (const float*)d_in[0];
    const float* rays_d  = (const float*)d_in[1];
    const float* nearv   = (const float*)d_in[2];
    const float* farv    = (const float*)d_in[3];
    const float* jitter  = (const float*)d_in[4];
    const float* density = (const float*)d_in[5];
    const float* W1      = (const float*)d_in[6];
    const float* b1      = (const float*)d_in[7];
    const float* W2      = (const float*)d_in[8];
    const float* b2      = (const float*)d_in[9];
    const float* Wsig    = (const float*)d_in[10];
    const float* bsig    = (const float*)d_in[11];
    const float* Wrgb    = (const float*)d_in[12];
    const float* brgb    = (const float*)d_in[13];

    const int n_rays = in_sizes[2];   // near has one entry per ray

    cudaFuncSetAttribute(render_kernel, cudaFuncAttributeMaxDynamicSharedMemorySize, SMEM_BYTES);

    pack_w2_kernel<<<(H * H + 127) / 128, 128>>>(W2);
    render_kernel<<<n_rays, 128, SMEM_BYTES>>>(rays_o, rays_d, nearv, farv, jitter, density,
                                               W1, b1, b2, Wsig, bsig, Wrgb, brgb,
                                               (float*)d_out);
}